// round 1
// baseline (speedup 1.0000x reference)
#include <cuda_runtime.h>
#include <cuda_bf16.h>
#include <math.h>

// ---------------------------------------------------------------------------
// MoE router (TOP_K=2, N_EXP=8). Output layout (float32, flattened tuple):
//   [0..8)                      used_capacity  (int counts as float)
//   [8 .. 8+N*8*C)              cb_weight[N,8,C]
//   [8+N*8*C .. 8+2*N*8*C)      sec_mask[N,8,C] (0.0/1.0)
// ---------------------------------------------------------------------------

#define N_EXP 8
#define MAXN 65536

__device__ int   g_eidx[2 * MAXN];  // [k*N + n] -> expert index of k-th choice
__device__ float g_pval[2 * MAXN];  // [k*N + n] -> softmax prob of that expert

// ---------------------------------------------------------------------------
// Kernel A: logits = x @ w_g^T, top-2 (lowest-index tie break), softmax probs.
// One warp per token; w_g (8x1024 fp32 = 32KB) staged in shared as float4.
// ---------------------------------------------------------------------------
__global__ void __launch_bounds__(256) router_topk_kernel(
    const float* __restrict__ x, const float* __restrict__ w_g, int N, int D)
{
    // D is assumed 1024 here (shape-static problem); shared sized for it.
    __shared__ float4 ws[N_EXP * 256];  // 8 * 256 float4 = 8*1024 floats

    const int tid  = threadIdx.x;
    const int warp = tid >> 5;
    const int lane = tid & 31;

    const float4* wg4 = reinterpret_cast<const float4*>(w_g);
#pragma unroll
    for (int r = 0; r < 8; r++) {
        int idx = r * 256 + tid;
        ws[idx] = wg4[idx];
    }
    __syncthreads();

    const int token = blockIdx.x * 8 + warp;
    if (token >= N) return;

    const float4* x4 = reinterpret_cast<const float4*>(x) + (size_t)token * 256;

    float acc[N_EXP];
#pragma unroll
    for (int e = 0; e < N_EXP; e++) acc[e] = 0.0f;

#pragma unroll
    for (int j = 0; j < 8; j++) {
        float4 xv = x4[j * 32 + lane];
#pragma unroll
        for (int e = 0; e < N_EXP; e++) {
            float4 wv = ws[e * 256 + j * 32 + lane];
            acc[e] += xv.x * wv.x + xv.y * wv.y + xv.z * wv.z + xv.w * wv.w;
        }
    }

    // warp reduction of 8 accumulators
#pragma unroll
    for (int off = 16; off > 0; off >>= 1) {
#pragma unroll
        for (int e = 0; e < N_EXP; e++)
            acc[e] += __shfl_down_sync(0xFFFFFFFFu, acc[e], off);
    }

    if (lane == 0) {
        // top-1 with lowest-index tie break (strict >)
        int e0 = 0; float b0 = acc[0];
#pragma unroll
        for (int e = 1; e < N_EXP; e++)
            if (acc[e] > b0) { b0 = acc[e]; e0 = e; }
        // top-2 excluding e0
        int e1 = (e0 == 0) ? 1 : 0; float b1 = acc[e1];
#pragma unroll
        for (int e = 0; e < N_EXP; e++)
            if (e != e0 && acc[e] > b1) { b1 = acc[e]; e1 = e; }

        // softmax (max = b0)
        float sum = 0.0f;
#pragma unroll
        for (int e = 0; e < N_EXP; e++) sum += expf(acc[e] - b0);
        float inv = 1.0f / sum;
        float p0 = inv;                    // expf(0) * inv
        float p1 = expf(b1 - b0) * inv;

        g_eidx[token]     = e0;
        g_eidx[N + token] = e1;
        g_pval[token]     = p0;
        g_pval[N + token] = p1;
    }
}

// ---------------------------------------------------------------------------
// Kernel B: ordered rank assignment (cumsum over flattened [K*N] entries in
// k-major/token order, per expert), capacity drop, scatter of cb_weight and
// sec_mask, used_capacity. Single block, deterministic hierarchical scan.
// ---------------------------------------------------------------------------
__global__ void __launch_bounds__(1024) rank_scatter_kernel(
    float* __restrict__ out, int N, int C, int per_thread)
{
    const int t    = threadIdx.x;
    const int warp = t >> 5;
    const int lane = t & 31;
    const int nwarps = blockDim.x >> 5;
    const int total = 2 * N;

    int el[8];     // expert per local entry (per_thread <= 8)
    int cnt[N_EXP];
#pragma unroll
    for (int e = 0; e < N_EXP; e++) cnt[e] = 0;

    const int base_i = t * per_thread;
    for (int j = 0; j < per_thread; j++) {
        int i = base_i + j;
        if (i < total) {
            int e = g_eidx[i];
            el[j] = e;
            cnt[e]++;
        } else {
            el[j] = -1;
        }
    }

    // warp inclusive scan per expert
    int inc[N_EXP];
#pragma unroll
    for (int e = 0; e < N_EXP; e++) inc[e] = cnt[e];
#pragma unroll
    for (int off = 1; off < 32; off <<= 1) {
#pragma unroll
        for (int e = 0; e < N_EXP; e++) {
            int v = __shfl_up_sync(0xFFFFFFFFu, inc[e], off);
            if (lane >= off) inc[e] += v;
        }
    }

    __shared__ int warpTot[N_EXP][32];
    __shared__ int warpBase[N_EXP][32];
    __shared__ int totals[N_EXP];

    if (lane == 31) {
#pragma unroll
        for (int e = 0; e < N_EXP; e++) warpTot[e][warp] = inc[e];
    }
    __syncthreads();

    if (warp == 0) {
        int v[N_EXP], s[N_EXP];
#pragma unroll
        for (int e = 0; e < N_EXP; e++) {
            v[e] = (lane < nwarps) ? warpTot[e][lane] : 0;
            s[e] = v[e];
        }
#pragma unroll
        for (int off = 1; off < 32; off <<= 1) {
#pragma unroll
            for (int e = 0; e < N_EXP; e++) {
                int u = __shfl_up_sync(0xFFFFFFFFu, s[e], off);
                if (lane >= off) s[e] += u;
            }
        }
#pragma unroll
        for (int e = 0; e < N_EXP; e++) warpBase[e][lane] = s[e] - v[e];
        if (lane == 31) {
#pragma unroll
            for (int e = 0; e < N_EXP; e++) totals[e] = s[e];
        }
    }
    __syncthreads();

    // exclusive running rank at start of this thread's chunk
    int run[N_EXP];
#pragma unroll
    for (int e = 0; e < N_EXP; e++)
        run[e] = warpBase[e][warp] + (inc[e] - cnt[e]);

    const size_t cbw_off  = 8;
    const size_t mask_off = 8 + (size_t)N * N_EXP * (size_t)C;

    for (int j = 0; j < per_thread; j++) {
        int i = base_i + j;
        if (i >= total) break;
        int e = el[j];
        int r = run[e]++;
        if (r < C) {
            int k = (i >= N) ? 1 : 0;
            int n = i - k * N;
            float w = g_pval[i];
            size_t pos = ((size_t)n * N_EXP + e) * (size_t)C + r;
            out[cbw_off + pos]  = w;
            out[mask_off + pos] = 1.0f;
        }
    }

    if (t < N_EXP) {
        int uc = totals[t];
        if (uc > C) uc = C;
        out[t] = (float)uc;
    }
}

// ---------------------------------------------------------------------------
extern "C" void kernel_launch(void* const* d_in, const int* in_sizes, int n_in,
                              void* d_out, int out_size)
{
    const float* x   = (const float*)d_in[0];
    const float* w_g = (const float*)d_in[1];
    float* out = (float*)d_out;

    const int D = in_sizes[1] / N_EXP;        // 1024
    const int N = in_sizes[0] / D;            // 4096 tokens

    // capacity: floor(K * 1.25 * N / E), round up to even, min 4
    int C = (int)floorf(2.0f * 1.25f * (float)N / (float)N_EXP);
    C += (C & 1);
    if (C < 4) C = 4;

    // 1) zero the full output (cb_weight/sec_mask are ~all zeros)
    cudaMemsetAsync(d_out, 0, (size_t)out_size * sizeof(float));

    // 2) router: logits + top-2 + softmax probs
    int blocks = (N + 7) / 8;
    router_topk_kernel<<<blocks, 256>>>(x, w_g, N, D);

    // 3) ordered ranks + capacity drop + scatter + used_capacity
    int per_thread = (2 * N + 1023) / 1024;   // 8 for N=4096
    rank_scatter_kernel<<<1, 1024>>>(out, N, C, per_thread);
}

// round 2
// speedup vs baseline: 1.0208x; 1.0208x over previous
#include <cuda_runtime.h>
#include <cuda_bf16.h>
#include <math.h>

// ---------------------------------------------------------------------------
// MoE router (TOP_K=2, N_EXP=8). Output layout (float32, flattened tuple):
//   [0..8)                      used_capacity
//   [8 .. 8+N*8*C)              cb_weight[N,8,C]
//   [8+N*8*C .. 8+2*N*8*C)      sec_mask[N,8,C] (0.0/1.0)
// ---------------------------------------------------------------------------

#define N_EXP 8
#define MAXN 65536

__device__ int   g_eidx[2 * MAXN];   // [k*N + n] -> expert of k-th choice
__device__ float g_pval[2 * MAXN];   // [k*N + n] -> softmax prob of that expert
__device__ int2  g_entry[MAXN * N_EXP]; // per (n,e): {rank or -1, weight bits}

// ---------------------------------------------------------------------------
// Kernel A: logits = x @ w_g^T, top-2 (lowest-index tie break), softmax probs.
// One warp per token; w_g staged in shared as float4.
// ---------------------------------------------------------------------------
__global__ void __launch_bounds__(256) router_topk_kernel(
    const float* __restrict__ x, const float* __restrict__ w_g, int N, int D)
{
    __shared__ float4 ws[N_EXP * 256];  // 8 * 1024 floats (D=1024)

    const int tid  = threadIdx.x;
    const int warp = tid >> 5;
    const int lane = tid & 31;

    const float4* wg4 = reinterpret_cast<const float4*>(w_g);
#pragma unroll
    for (int r = 0; r < 8; r++) {
        int idx = r * 256 + tid;
        ws[idx] = wg4[idx];
    }
    __syncthreads();

    const int token = blockIdx.x * 8 + warp;
    if (token >= N) return;

    const float4* x4 = reinterpret_cast<const float4*>(x) + (size_t)token * 256;

    float acc[N_EXP];
#pragma unroll
    for (int e = 0; e < N_EXP; e++) acc[e] = 0.0f;

#pragma unroll
    for (int j = 0; j < 8; j++) {
        float4 xv = x4[j * 32 + lane];
#pragma unroll
        for (int e = 0; e < N_EXP; e++) {
            float4 wv = ws[e * 256 + j * 32 + lane];
            acc[e] += xv.x * wv.x + xv.y * wv.y + xv.z * wv.z + xv.w * wv.w;
        }
    }

#pragma unroll
    for (int off = 16; off > 0; off >>= 1) {
#pragma unroll
        for (int e = 0; e < N_EXP; e++)
            acc[e] += __shfl_down_sync(0xFFFFFFFFu, acc[e], off);
    }

    if (lane == 0) {
        int e0 = 0; float b0 = acc[0];
#pragma unroll
        for (int e = 1; e < N_EXP; e++)
            if (acc[e] > b0) { b0 = acc[e]; e0 = e; }
        int e1 = (e0 == 0) ? 1 : 0; float b1 = acc[e1];
#pragma unroll
        for (int e = 0; e < N_EXP; e++)
            if (e != e0 && acc[e] > b1) { b1 = acc[e]; e1 = e; }

        float sum = 0.0f;
#pragma unroll
        for (int e = 0; e < N_EXP; e++) sum += expf(acc[e] - b0);
        float inv = 1.0f / sum;
        float p0 = inv;
        float p1 = expf(b1 - b0) * inv;

        g_eidx[token]     = e0;
        g_eidx[N + token] = e1;
        g_pval[token]     = p0;
        g_pval[N + token] = p1;
    }
}

// ---------------------------------------------------------------------------
// Kernel B: ordered per-expert rank (cumsum in k-major, token order) via
// match_any + popc within warp, per-expert cross-warp scan by warps 0..7.
// Writes compact (rank, weight) table + used_capacity. Single block, no
// local-memory indexed arrays.
// ---------------------------------------------------------------------------
__global__ void __launch_bounds__(1024) rank_kernel(
    float* __restrict__ out, int N, int C)
{
    const int tid  = threadIdx.x;
    const int warp = tid >> 5;
    const int lane = tid & 31;
    const int total = 2 * N;
    const int rows  = N * N_EXP;

    // reset per-(n,e) table to "empty"
    for (int i = tid; i < rows; i += 1024)
        g_entry[i] = make_int2(-1, 0);

    __shared__ int warpcnt[N_EXP][32];
    __shared__ int basesh[N_EXP][32];
    __shared__ int running[N_EXP];
    if (tid < N_EXP) running[tid] = 0;

    const int rounds = (total + 1023) >> 10;
    for (int rd = 0; rd < rounds; rd++) {
        const int i = rd * 1024 + tid;
        const int e = (i < total) ? g_eidx[i] : -1;

        if (tid < N_EXP * 32) ((int*)warpcnt)[tid] = 0;
        __syncthreads();

        unsigned m = __match_any_sync(0xFFFFFFFFu, e);
        int lrank  = __popc(m & ((1u << lane) - 1u));
        int leader = __ffs(m) - 1;
        if (e >= 0 && lane == leader)
            warpcnt[e][warp] = __popc(m);
        __syncthreads();

        if (warp < N_EXP) {
            int runv = running[warp];
            int v = warpcnt[warp][lane];
            int s = v;
#pragma unroll
            for (int off = 1; off < 32; off <<= 1) {
                int u = __shfl_up_sync(0xFFFFFFFFu, s, off);
                if (lane >= off) s += u;
            }
            basesh[warp][lane] = runv + s - v;   // exclusive + running
            if (lane == 31) running[warp] = runv + s;
        }
        __syncthreads();

        if (e >= 0) {
            int r = basesh[e][warp] + lrank;
            if (r < C) {
                int k = (i >= N) ? 1 : 0;
                int n = i - k * N;
                g_entry[n * N_EXP + e] =
                    make_int2(r, __float_as_int(g_pval[i]));
            }
        }
        __syncthreads();
    }

    if (tid < N_EXP) {
        int uc = running[tid];
        if (uc > C) uc = C;
        out[tid] = (float)uc;
    }
}

// ---------------------------------------------------------------------------
// Kernel C: fused zero-fill + scatter. One warp per (n,e) row: stream zeros
// with float4 stores into cb_weight and sec_mask, patching the (at most one)
// nonzero element inline. Pure store-bandwidth bound.
// ---------------------------------------------------------------------------
__global__ void __launch_bounds__(256) fill_kernel(
    float* __restrict__ out, int N, int C)
{
    const int gw   = (blockIdx.x * blockDim.x + threadIdx.x) >> 5;
    const int lane = threadIdx.x & 31;
    const int rows = N * N_EXP;
    if (gw >= rows) return;

    int2 ent = g_entry[gw];
    const int   r = ent.x;
    const float w = __int_as_float(ent.y);

    if ((C & 3) == 0) {
        const int C4 = C >> 2;
        float4* cbw = reinterpret_cast<float4*>(out + 8) + (size_t)gw * C4;
        float4* msk = cbw + (size_t)rows * C4;
        const int rc = (r >= 0) ? (r >> 2) : -1;
        const int rl = r & 3;
        for (int c = lane; c < C4; c += 32) {
            float4 z = make_float4(0.f, 0.f, 0.f, 0.f);
            float4 mm = make_float4(0.f, 0.f, 0.f, 0.f);
            if (c == rc) {
                reinterpret_cast<float*>(&z)[rl]  = w;
                reinterpret_cast<float*>(&mm)[rl] = 1.0f;
            }
            cbw[c] = z;
            msk[c] = mm;
        }
    } else {
        float* cbw = out + 8 + (size_t)gw * C;
        float* msk = cbw + (size_t)rows * C;
        for (int c = lane; c < C; c += 32) {
            cbw[c] = (c == r) ? w    : 0.0f;
            msk[c] = (c == r) ? 1.0f : 0.0f;
        }
    }
}

// ---------------------------------------------------------------------------
extern "C" void kernel_launch(void* const* d_in, const int* in_sizes, int n_in,
                              void* d_out, int out_size)
{
    const float* x   = (const float*)d_in[0];
    const float* w_g = (const float*)d_in[1];
    float* out = (float*)d_out;

    const int D = in_sizes[1] / N_EXP;   // 1024
    const int N = in_sizes[0] / D;       // 4096 tokens

    int C = (int)floorf(2.0f * 1.25f * (float)N / (float)N_EXP);
    C += (C & 1);
    if (C < 4) C = 4;

    // 1) router: logits + top-2 + softmax probs
    int blocks = (N + 7) / 8;
    router_topk_kernel<<<blocks, 256>>>(x, w_g, N, D);

    // 2) ordered ranks + capacity drop -> compact table + used_capacity
    rank_kernel<<<1, 1024>>>(out, N, C);

    // 3) fused zero-fill + scatter of cb_weight / sec_mask
    int rows = N * N_EXP;
    int fill_blocks = (rows * 32 + 255) / 256;
    fill_kernel<<<fill_blocks, 256>>>(out, N, C);
}